// round 8
// baseline (speedup 1.0000x reference)
#include <cuda_runtime.h>
#include <cstdint>

// out[c, i, j, k, l] = tb[c,0,i] * tb[c,1,j] * tb[c,2,k] * tb[c,3,l]
// tb = tensor + bias, shapes (C=2048, 4, 16). Output (C, 16,16,16,16) fp32.
//
// Pure store-bandwidth kernel: 512 MB out, ~1 MB in.
// R8 = R7 (32768 CTAs, one i-slice of 16 KB each, st.global.v8.b32) with
// the smem staging + __syncthreads removed: each thread __ldg's exactly the
// 12 input values it needs (all independent, L2-hit for 15/16 CTAs per
// channel). CTA critical path = loads -> 3 FMUL -> 2 stores, no barrier.

static constexpr int LDIM = 16;
static constexpr int NFAC = 4;
static constexpr int THREADS = 256;

__device__ __forceinline__ void stg_v8(float* p,
                                       float a, float b, float c, float d,
                                       float e, float f, float g, float h)
{
    asm volatile(
        "st.global.v8.b32 [%0], {%1, %2, %3, %4, %5, %6, %7, %8};"
        :: "l"(p),
           "r"(__float_as_uint(a)), "r"(__float_as_uint(b)),
           "r"(__float_as_uint(c)), "r"(__float_as_uint(d)),
           "r"(__float_as_uint(e)), "r"(__float_as_uint(f)),
           "r"(__float_as_uint(g)), "r"(__float_as_uint(h))
        : "memory");
}

__global__ __launch_bounds__(THREADS, 8)
void tpe_kernel(const float* __restrict__ tensor,
                const float* __restrict__ bias,
                float* __restrict__ out)
{
    const int b = blockIdx.x;
    const int c = b >> 4;          // channel
    const int i = b & 15;          // i slice: this CTA writes out[c, i, :, :, :]
    const int t = threadIdx.x;

    // float8 index within the i-slice: r = t + 256*jh, jh in {0,1}.
    //   l-half lh = r & 1, k = (r>>1) & 15, jlow = (r>>5) & 7 (from t);
    //   j = jlow | (jh<<3).
    const int lh   = t & 1;
    const int k    = (t >> 1) & 15;
    const int jlow = (t >> 5) & 7;

    const int ofs = c * (NFAC * LDIM);

    // Direct loads of the 12 needed inputs (independent; L2-hit for 15/16
    // CTAs of each channel since 16 CTAs share the same 256 B).
    const float t0  = __ldg(tensor + ofs + i)              + __ldg(bias + ofs + i);
    const float p2  = __ldg(tensor + ofs + 2 * LDIM + k)   + __ldg(bias + ofs + 2 * LDIM + k);
    const float s1a = __ldg(tensor + ofs + LDIM + jlow)     + __ldg(bias + ofs + LDIM + jlow);
    const float s1b = __ldg(tensor + ofs + LDIM + jlow + 8) + __ldg(bias + ofs + LDIM + jlow + 8);

    // s3 half-row: 8 floats as two float4 pairs (ofs+48+lh*8 is 16B-aligned).
    const float4* t3 = (const float4*)(tensor + ofs + 3 * LDIM + lh * 8);
    const float4* b3 = (const float4*)(bias   + ofs + 3 * LDIM + lh * 8);
    const float4 ta = __ldg(t3),     ba = __ldg(b3);
    const float4 tc = __ldg(t3 + 1), bc = __ldg(b3 + 1);

    float v3[8];
    v3[0] = ta.x + ba.x;  v3[1] = ta.y + ba.y;
    v3[2] = ta.z + ba.z;  v3[3] = ta.w + ba.w;
    v3[4] = tc.x + bc.x;  v3[5] = tc.y + bc.y;
    v3[6] = tc.z + bc.z;  v3[7] = tc.w + bc.w;

    const float a0 = t0 * p2;

    float* ob = out + (size_t)c * 65536 + (size_t)i * 4096 + (size_t)t * 8;

    {
        const float a = a0 * s1a;
        stg_v8(ob,
               a * v3[0], a * v3[1], a * v3[2], a * v3[3],
               a * v3[4], a * v3[5], a * v3[6], a * v3[7]);
    }
    {
        const float a = a0 * s1b;
        stg_v8(ob + 2048,
               a * v3[0], a * v3[1], a * v3[2], a * v3[3],
               a * v3[4], a * v3[5], a * v3[6], a * v3[7]);
    }
}

extern "C" void kernel_launch(void* const* d_in, const int* in_sizes, int n_in,
                              void* d_out, int out_size)
{
    const float* tensor = (const float*)d_in[0];
    const float* bias   = (const float*)d_in[1];
    float* out          = (float*)d_out;

    const int C = in_sizes[0] / (NFAC * LDIM);   // 2048

    tpe_kernel<<<C * 16, THREADS>>>(tensor, bias, out);
}

// round 9
// speedup vs baseline: 1.0101x; 1.0101x over previous
#include <cuda_runtime.h>
#include <cstdint>

// out[c, i, j, k, l] = tb[c,0,i] * tb[c,1,j] * tb[c,2,k] * tb[c,3,l]
// tb = tensor + bias, shapes (C=2048, 4, 16). Output (C, 16,16,16,16) fp32.
//
// Pure store-bandwidth kernel: 512 MB out, ~1 MB in.
// R9 = R7 grain (32768 CTAs, one 16KB i-slice each, smem-staged inputs)
// with the egress path switched from 512 scattered STG.v8 wavefronts to a
// single 16KB cp.async.bulk (UBLKCP) smem->gmem store per CTA: compute the
// tile into smem, fence.proxy.async, one elected thread issues the bulk
// store and waits. DRAM sees large sequential bursts instead of finely
// interleaved 128B wavefronts from ~9700 warps.

static constexpr int LDIM = 16;
static constexpr int NFAC = 4;
static constexpr int THREADS = 256;
static constexpr int TILE_FLOATS = 4096;            // 16 KB
static constexpr int TILE_BYTES  = TILE_FLOATS * 4;

__global__ __launch_bounds__(THREADS, 8)
void tpe_kernel(const float* __restrict__ tensor,
                const float* __restrict__ bias,
                float* __restrict__ out)
{
    __shared__ float s[NFAC * LDIM];
    __shared__ __align__(128) float tile[TILE_FLOATS];

    const int b = blockIdx.x;
    const int c = b >> 4;          // channel
    const int i = b & 15;          // i slice: this CTA writes out[c, i, :, :, :]
    const int t = threadIdx.x;

    if (t < NFAC * LDIM) {
        const int g = c * (NFAC * LDIM) + t;
        s[t] = tensor[g] + bias[g];
    }
    __syncthreads();

    // float8 index within the i-slice: r = t + 256*jh, jh in {0,1}.
    //   l-half lh = r & 1, k = (r>>1) & 15, jlow = (r>>5) & 7 (from t);
    //   j = jlow | (jh<<3).
    const int lh   = t & 1;
    const int k    = (t >> 1) & 15;
    const int jlow = (t >> 5) & 7;

    const float p2 = s[2 * LDIM + k];
    float v3[8];
    #pragma unroll
    for (int m = 0; m < 8; ++m) v3[m] = s[3 * LDIM + lh * 8 + m];

    const float a0 = s[i] * p2;

    float4* tp = reinterpret_cast<float4*>(tile) + t * 2;  // thread's 2 float4 slots

    #pragma unroll
    for (int jh = 0; jh < 2; ++jh) {
        const float a = a0 * s[LDIM + jlow + (jh << 3)];
        float4 w0, w1;
        w0.x = a * v3[0]; w0.y = a * v3[1]; w0.z = a * v3[2]; w0.w = a * v3[3];
        w1.x = a * v3[4]; w1.y = a * v3[5]; w1.z = a * v3[6]; w1.w = a * v3[7];
        tp[jh * 512 + 0] = w0;
        tp[jh * 512 + 1] = w1;
    }
    __syncthreads();

    if (t == 0) {
        uint32_t saddr;
        asm("{ .reg .u64 a; cvta.to.shared.u64 a, %1; cvt.u32.u64 %0, a; }"
            : "=r"(saddr) : "l"(tile));
        float* gptr = out + (size_t)c * 65536 + (size_t)i * 4096;
        asm volatile("fence.proxy.async.shared::cta;" ::: "memory");
        asm volatile(
            "cp.async.bulk.global.shared::cta.bulk_group [%0], [%1], %2;"
            :: "l"(gptr), "r"(saddr), "r"(TILE_BYTES) : "memory");
        asm volatile("cp.async.bulk.commit_group;" ::: "memory");
        asm volatile("cp.async.bulk.wait_group 0;" ::: "memory");
    }
}

extern "C" void kernel_launch(void* const* d_in, const int* in_sizes, int n_in,
                              void* d_out, int out_size)
{
    const float* tensor = (const float*)d_in[0];
    const float* bias   = (const float*)d_in[1];
    float* out          = (float*)d_out;

    const int C = in_sizes[0] / (NFAC * LDIM);   // 2048

    tpe_kernel<<<C * 16, THREADS>>>(tensor, bias, out);
}